// round 16
// baseline (speedup 1.0000x reference)
#include <cuda_runtime.h>
#include <cuda_fp16.h>
#include <math.h>

// ---------------- problem constants ----------------
#define BB   4
#define TT   4
#define HH   56
#define WW_  56
#define CC   256
#define NHD  8
#define HD   32
#define WS_  7
#define SS_  3
#define NTOK 49
#define HID_ 1024
#define GH   224
#define GW   56
#define NW   256
#define BW   1024
#define MROWS (BW*NTOK)         // 50176
#define LL   (TT*HH*WW_)        // 12544
#define BLC  (BB*LL*CC)         // 12845056

// ---------------- scratch ----------------
__device__ __align__(16) __half g_xw_h [MROWS * CC];
__device__ __align__(16) __half g_qkv_h[MROWS * 3*CC];
__device__ __align__(16) __half g_y_h  [MROWS * CC];
__device__ float g_x1m [BB*LL*CC];
__device__ __align__(16) __half g_xn2_h[BB*LL*CC];
__device__ __align__(16) __half g_h_h  [BB*LL*HID_];
__device__ __align__(16) __half g_wqkv[3*CC*CC];
__device__ __align__(16) __half g_wproj[CC*CC];
__device__ __align__(16) __half g_wfc1[HID_*CC];
__device__ __align__(16) __half g_wfc2[CC*HID_];

// ---------------- fused weight convert ----------------
#define NQ_QKV (3*CC*CC/4)
#define NQ_PROJ (CC*CC/4)
#define NQ_FC1 (HID_*CC/4)
#define NQ_FC2 (CC*HID_/4)
#define NQ_TOT (NQ_QKV+NQ_PROJ+NQ_FC1+NQ_FC2)

__global__ __launch_bounds__(256) void k_f2h_all(
    const float* __restrict__ qkvw, const float* __restrict__ projw,
    const float* __restrict__ fc1w, const float* __restrict__ fc2w,
    __half* __restrict__ dqkv, __half* __restrict__ dproj,
    __half* __restrict__ dfc1, __half* __restrict__ dfc2)
{
    int i = blockIdx.x * 256 + threadIdx.x;
    if (i >= NQ_TOT) return;
    const float* src; __half* dst; int j = i;
    if (j < NQ_QKV)                 { src = qkvw; dst = dqkv; }
    else if ((j -= NQ_QKV) < NQ_PROJ) { src = projw; dst = dproj; }
    else if ((j -= NQ_PROJ) < NQ_FC1) { src = fc1w; dst = dfc1; }
    else { j -= NQ_FC1; src = fc2w; dst = dfc2; }
    float4 v = ((const float4*)src)[j];
    ((__half2*)dst)[2 * j]     = __floats2half2_rn(v.x, v.y);
    ((__half2*)dst)[2 * j + 1] = __floats2half2_rn(v.z, v.w);
}

// ---------------- LN: one warp per row ----------------
__device__ __forceinline__ void warp_ln(const float4 v0, const float4 v1,
                                        float& mean, float& rstd) {
    float s  = v0.x + v0.y + v0.z + v0.w + v1.x + v1.y + v1.z + v1.w;
    float sq = v0.x*v0.x + v0.y*v0.y + v0.z*v0.z + v0.w*v0.w
             + v1.x*v1.x + v1.y*v1.y + v1.z*v1.z + v1.w*v1.w;
    #pragma unroll
    for (int o = 16; o; o >>= 1) {
        s  += __shfl_xor_sync(0xffffffffu, s,  o);
        sq += __shfl_xor_sync(0xffffffffu, sq, o);
    }
    mean = s * (1.0f / CC);
    float var = sq * (1.0f / CC) - mean * mean;
    rstd = rsqrtf(var + 1e-5f);
}
__device__ __forceinline__ void ln_emit_h(__half* dst, float4 v0, float4 v1,
                                          const float4 g0, const float4 g1,
                                          const float4 b0, const float4 b1,
                                          float m, float rs, int lane) {
    float4 o0, o1;
    o0.x = (v0.x - m) * rs * g0.x + b0.x; o0.y = (v0.y - m) * rs * g0.y + b0.y;
    o0.z = (v0.z - m) * rs * g0.z + b0.z; o0.w = (v0.w - m) * rs * g0.w + b0.w;
    o1.x = (v1.x - m) * rs * g1.x + b1.x; o1.y = (v1.y - m) * rs * g1.y + b1.y;
    o1.z = (v1.z - m) * rs * g1.z + b1.z; o1.w = (v1.w - m) * rs * g1.w + b1.w;
    __half2* d0 = (__half2*)(dst + lane * 4);
    d0[0] = __floats2half2_rn(o0.x, o0.y);
    d0[1] = __floats2half2_rn(o0.z, o0.w);
    __half2* d1 = (__half2*)(dst + 128 + lane * 4);
    d1[0] = __floats2half2_rn(o1.x, o1.y);
    d1[1] = __floats2half2_rn(o1.z, o1.w);
}

__global__ __launch_bounds__(256) void k_ln1_shift_win(
    const float* __restrict__ x1, const float* __restrict__ g, const float* __restrict__ b)
{
    int warp = threadIdx.x >> 5, lane = threadIdx.x & 31;
    int row = blockIdx.x * 8 + warp;
    int bw = row / NTOK, n = row - bw * NTOK;
    int bat = bw >> 8, w = bw & 255;
    int hs = (w >> 3) * WS_ + n / WS_;
    int ws = (w & 7) * WS_ + n % WS_;
    int h0 = hs + SS_; if (h0 >= GH) h0 -= GH;
    int w0 = ws + SS_; if (w0 >= GW) w0 -= GW;
    const float4* src = (const float4*)(x1 + ((size_t)bat * LL + (size_t)h0 * GW + w0) * CC);
    float4 v0 = src[lane], v1 = src[lane + 32];
    float m, rs; warp_ln(v0, v1, m, rs);
    float4 g0 = ((const float4*)g)[lane], g1 = ((const float4*)g)[lane + 32];
    float4 b0 = ((const float4*)b)[lane], b1 = ((const float4*)b)[lane + 32];
    ln_emit_h(g_xw_h + (size_t)row * CC, v0, v1, g0, g1, b0, b1, m, rs, lane);
}

__global__ __launch_bounds__(256) void k_ln2(
    const float* __restrict__ g, const float* __restrict__ b)
{
    int warp = threadIdx.x >> 5, lane = threadIdx.x & 31;
    int row = blockIdx.x * 8 + warp;
    const float4* src = (const float4*)(g_x1m + (size_t)row * CC);
    float4 v0 = src[lane], v1 = src[lane + 32];
    float m, rs; warp_ln(v0, v1, m, rs);
    float4 g0 = ((const float4*)g)[lane], g1 = ((const float4*)g)[lane + 32];
    float4 b0 = ((const float4*)b)[lane], b1 = ((const float4*)b)[lane + 32];
    ln_emit_h(g_xn2_h + (size_t)row * CC, v0, v1, g0, g1, b0, b1, m, rs, lane);
}

// ---------------- common helpers ----------------
__device__ __forceinline__ unsigned smem_u32(const void* p) {
    unsigned a;
    asm("{ .reg .u64 t; cvta.to.shared.u64 t, %1; cvt.u32.u64 %0, t; }" : "=r"(a) : "l"(p));
    return a;
}
__device__ __forceinline__ void cp16(unsigned dst, const void* src) {
    asm volatile("cp.async.cg.shared.global [%0], [%1], 16;" :: "r"(dst), "l"(src));
}
#define CP_COMMIT() asm volatile("cp.async.commit_group;" ::: "memory")

__device__ __forceinline__ void mma16816(float* c, const unsigned* a, unsigned b0, unsigned b1) {
    asm volatile("mma.sync.aligned.m16n8k16.row.col.f32.f16.f16.f32 "
                 "{%0,%1,%2,%3}, {%4,%5,%6,%7}, {%8,%9}, {%0,%1,%2,%3};"
                 : "+f"(c[0]), "+f"(c[1]), "+f"(c[2]), "+f"(c[3])
                 : "r"(a[0]), "r"(a[1]), "r"(a[2]), "r"(a[3]), "r"(b0), "r"(b1));
}
__device__ __forceinline__ void ldsm4(unsigned* r, unsigned addr) {
    asm volatile("ldmatrix.sync.aligned.m8n8.x4.shared.b16 {%0,%1,%2,%3}, [%4];"
                 : "=r"(r[0]), "=r"(r[1]), "=r"(r[2]), "=r"(r[3]) : "r"(addr));
}

// ================= fp16 mma GEMM: BK=32, 4-stage cp.async, 1 barrier/chunk =================
#define BM 128
#define BN 128
#define BK 32
#define NSTG 4
#define SROW 40                        // halves per smem row (80B; 20w -> conflict-free ldsm)
#define MAT_B (BM * SROW * 2)          // bytes per matrix per stage = 10240
#define STAGE_B (2 * MAT_B)            // A+B per stage = 20480
#define GEMM_SMEM (NSTG * STAGE_B)     // 81920

template<int EPI>
__global__ __launch_bounds__(256, 2) void k_gemm_h(
    const __half* __restrict__ A, const __half* __restrict__ Wt,
    const float* __restrict__ bias, void* __restrict__ CoutV,
    int Ntot, int K,
    const float* __restrict__ res, float* __restrict__ out2)
{
    extern __shared__ __half dsm[];
    unsigned sbase = smem_u32(dsm);

    int t = threadIdx.x, lane = t & 31, warp = t >> 5;
    int wm = (warp & 3) * 32, wn = (warp >> 2) * 64;
    int grp = lane >> 2, qid = lane & 3;
    int m0 = blockIdx.y * BM, n0 = blockIdx.x * BN;

    float acc[2][8][4];
    #pragma unroll
    for (int mt = 0; mt < 2; mt++)
        #pragma unroll
        for (int nt = 0; nt < 8; nt++)
            #pragma unroll
            for (int i = 0; i < 4; i++) acc[mt][nt][i] = 0.f;

    // loader: per matrix 512 chunks (128 rows x 4 segs of 16B); thread t -> rows t>>2, t>>2+64
    int lrow = t >> 2, lseg = t & 3;
    const __half* Ap0 = A  + (size_t)(m0 + lrow) * K + lseg * 8;
    const __half* Ap1 = A  + (size_t)(m0 + lrow + 64) * K + lseg * 8;
    const __half* Bp0 = Wt + (size_t)(n0 + lrow) * K + lseg * 8;
    const __half* Bp1 = Wt + (size_t)(n0 + lrow + 64) * K + lseg * 8;
    unsigned doffA0 = (lrow * SROW + lseg * 8) * 2;
    unsigned doffA1 = ((lrow + 64) * SROW + lseg * 8) * 2;

    // ldmatrix per-lane bases (halves)
    int ar = (lane & 7) + ((lane >> 3) & 1) * 8, ac = (lane >> 4) * 8;
    int aoff = (wm + ar) * SROW + ac;
    int br = (lane & 7) + (lane >> 4) * 8, bc = ((lane >> 3) & 1) * 8;
    int boff = (wn + br) * SROW + bc;

    int nk = K / BK;

    // prologue: issue stages 0..NSTG-2
    #pragma unroll
    for (int s = 0; s < NSTG - 1; s++) {
        unsigned st = sbase + s * STAGE_B;
        int k0 = s * BK;
        cp16(st + doffA0, Ap0 + k0);
        cp16(st + doffA1, Ap1 + k0);
        cp16(st + MAT_B + doffA0, Bp0 + k0);
        cp16(st + MAT_B + doffA1, Bp1 + k0);
        CP_COMMIT();
    }

    for (int ck = 0; ck < nk; ck++) {
        asm volatile("cp.async.wait_group %0;" :: "n"(NSTG - 2) : "memory");
        __syncthreads();
        // issue stage ck+NSTG-1 (safe: readers of that slot retired before this barrier)
        if (ck + NSTG - 1 < nk) {
            unsigned st = sbase + ((ck + NSTG - 1) & (NSTG - 1)) * STAGE_B;
            int k0 = (ck + NSTG - 1) * BK;
            cp16(st + doffA0, Ap0 + k0);
            cp16(st + doffA1, Ap1 + k0);
            cp16(st + MAT_B + doffA0, Bp0 + k0);
            cp16(st + MAT_B + doffA1, Bp1 + k0);
        }
        CP_COMMIT();   // keep group count in lockstep even on tail iterations

        unsigned aA = sbase + (ck & (NSTG - 1)) * STAGE_B;
        unsigned aB = aA + MAT_B;
        #pragma unroll
        for (int ks = 0; ks < 2; ks++) {
            unsigned a[2][4];
            ldsm4(a[0], aA + (aoff + ks * 16) * 2);
            ldsm4(a[1], aA + (aoff + 16 * SROW + ks * 16) * 2);
            #pragma unroll
            for (int np = 0; np < 4; np++) {
                unsigned bf[4];
                ldsm4(bf, aB + (boff + np * 16 * SROW + ks * 16) * 2);
                mma16816(acc[0][np * 2    ], a[0], bf[0], bf[1]);
                mma16816(acc[0][np * 2 + 1], a[0], bf[2], bf[3]);
                mma16816(acc[1][np * 2    ], a[1], bf[0], bf[1]);
                mma16816(acc[1][np * 2 + 1], a[1], bf[2], bf[3]);
            }
        }
    }

    // epilogue
    #pragma unroll
    for (int mt = 0; mt < 2; mt++) {
        #pragma unroll
        for (int half = 0; half < 2; half++) {
            int r = m0 + wm + mt * 16 + grp + half * 8;
            size_t dstrow = 0;
            if (EPI == 3) {
                int bw = r / NTOK, n = r - bw * NTOK;
                int bat = bw >> 8, w = bw & 255;
                int hs = (w >> 3) * WS_ + n / WS_;
                int ws = (w & 7) * WS_ + n % WS_;
                int h0 = hs + SS_; if (h0 >= GH) h0 -= GH;
                int w0 = ws + SS_; if (w0 >= GW) w0 -= GW;
                dstrow = ((size_t)bat * LL + (size_t)h0 * GW + w0) * CC;
            }
            #pragma unroll
            for (int nt = 0; nt < 8; nt++) {
                int c = n0 + wn + nt * 8 + qid * 2;
                float v0 = acc[mt][nt][half * 2 + 0] + bias[c];
                float v1 = acc[mt][nt][half * 2 + 1] + bias[c + 1];
                if (EPI == 0) {
                    *(__half2*)((__half*)CoutV + (size_t)r * Ntot + c) = __floats2half2_rn(v0, v1);
                } else if (EPI == 1) {
                    v0 = 0.5f * v0 * (1.0f + erff(v0 * 0.70710678118654752f));
                    v1 = 0.5f * v1 * (1.0f + erff(v1 * 0.70710678118654752f));
                    *(__half2*)((__half*)CoutV + (size_t)r * Ntot + c) = __floats2half2_rn(v0, v1);
                } else if (EPI == 2) {
                    float* Cout = (float*)CoutV;
                    float2 rr = *(const float2*)(res + (size_t)r * Ntot + c);
                    *(float2*)(Cout + (size_t)r * Ntot + c) = make_float2(rr.x + v0, rr.y + v1);
                } else {
                    float* Cout = (float*)CoutV;
                    size_t off = dstrow + c;
                    if (out2) *(float2*)(out2 + off) = make_float2(v0, v1);
                    float2 rr = *(const float2*)(res + off);
                    *(float2*)(Cout + off) = make_float2(rr.x + v0, rr.y + v1);
                }
            }
        }
    }
}

// ---------------- window attention: fp16 smem operands, fp32 accumulation ----------------
#define QPH 40    // halves per q/k/v smem row (80B, 16B-aligned)
#define SP 52     // S row stride (floats)
#define NPAD 52

__global__ __launch_bounds__(128, 8) void k_attn(const float* __restrict__ rpb)
{
    int bw = blockIdx.x >> 3;
    int h  = blockIdx.x & 7;
    __shared__ __half qs[NPAD][QPH];
    __shared__ __half ks[NPAD][QPH];
    __shared__ __half vs[NPAD][QPH];
    __shared__ float S [NPAD][SP];
    __shared__ float bias_s[169];
    __shared__ int   reg_s[NPAD];
    int t = threadIdx.x;
    const float scale = 0.17677669529663687f;

    // raw fp16 copy: 3 matrices x 49 rows x 4 chunks(16B)
    const __half* base = g_qkv_h + (size_t)bw * NTOK * (3 * CC) + h * HD;
    for (int idx = t; idx < 3 * NTOK * 4; idx += 128) {
        int mat = idx / (NTOK * 4), ch = idx - mat * NTOK * 4;
        int n = ch >> 2, seg = ch & 3;
        uint4 u = *(const uint4*)(base + (size_t)n * (3 * CC) + mat * CC + seg * 8);
        __half* dst = (mat == 0 ? &qs[n][0] : mat == 1 ? &ks[n][0] : &vs[n][0]);
        *(uint4*)(dst + seg * 8) = u;
    }
    for (int idx = t; idx < 169; idx += 128) bias_s[idx] = rpb[idx * NHD + h];
    if (t < NPAD) {
        int rv = 0;
        if (t < NTOK) {
            int w = bw & 255;
            int hs = (w >> 3) * WS_ + t / WS_;
            int ws = (w & 7) * WS_ + t % WS_;
            int rc = hs < (GH - WS_) ? 0 : (hs < (GH - SS_) ? 1 : 2);
            int cc = ws < (GW - WS_) ? 0 : (ws < (GW - SS_) ? 1 : 2);
            rv = rc * 3 + cc;
        }
        reg_s[t] = rv;
    }
    __syncthreads();

    // S = (q @ k^T)*scale + bias + mask : 13x13 tiles of 4x4, fp32 accumulate
    for (int tile = t; tile < 169; tile += 128) {
        int it = tile / 13, jt = tile - it * 13;
        int i0 = it * 4, j0 = jt * 4;
        float a[4][4];
        #pragma unroll
        for (int ii = 0; ii < 4; ii++)
            #pragma unroll
            for (int jj = 0; jj < 4; jj++) a[ii][jj] = 0.f;
        #pragma unroll
        for (int dc = 0; dc < 4; dc++) {       // 8 halves per chunk
            float qf[4][8], kf[4][8];
            #pragma unroll
            for (int r = 0; r < 4; r++) {
                uint4 u = *(const uint4*)(&qs[i0 + r][dc * 8]);
                float2 f0 = __half22float2(*(__half2*)&u.x);
                float2 f1 = __half22float2(*(__half2*)&u.y);
                float2 f2 = __half22float2(*(__half2*)&u.z);
                float2 f3 = __half22float2(*(__half2*)&u.w);
                qf[r][0]=f0.x; qf[r][1]=f0.y; qf[r][2]=f1.x; qf[r][3]=f1.y;
                qf[r][4]=f2.x; qf[r][5]=f2.y; qf[r][6]=f3.x; qf[r][7]=f3.y;
            }
            #pragma unroll
            for (int r = 0; r < 4; r++) {
                uint4 u = *(const uint4*)(&ks[j0 + r][dc * 8]);
                float2 f0 = __half22float2(*(__half2*)&u.x);
                float2 f1 = __half22float2(*(__half2*)&u.y);
                float2 f2 = __half22float2(*(__half2*)&u.z);
                float2 f3 = __half22float2(*(__half2*)&u.w);
                kf[r][0]=f0.x; kf[r][1]=f0.y; kf[r][2]=f1.x; kf[r][3]=f1.y;
                kf[r][4]=f2.x; kf[r][5]=f2.y; kf[r][6]=f3.x; kf[r][7]=f3.y;
            }
            #pragma unroll
            for (int ii = 0; ii < 4; ii++)
                #pragma unroll
                for (int jj = 0; jj < 4; jj++)
                    #pragma unroll
                    for (int d = 0; d < 8; d++)
                        a[ii][jj] = fmaf(qf[ii][d], kf[jj][d], a[ii][jj]);
        }
        #pragma unroll
        for (int ii = 0; ii < 4; ii++) {
            int i = i0 + ii;
            int yi = i / 7, xi = i - yi * 7, ri = reg_s[i];
            float4 o;
            float* op = &o.x;
            #pragma unroll
            for (int jj = 0; jj < 4; jj++) {
                int j = j0 + jj;
                float s = a[ii][jj] * scale;
                if (i < NTOK && j < NTOK) {
                    int yj = j / 7, xj = j - yj * 7;
                    s += bias_s[(yi - yj + 6) * 13 + (xi - xj + 6)];
                    if (ri != reg_s[j]) s -= 100.f;
                }
                op[jj] = s;
            }
            *(float4*)&S[i][j0] = o;
        }
    }
    __syncthreads();

    // softmax rows (fp32)
    int wid = t >> 5, lane = t & 31;
    for (int i = wid; i < NTOK; i += 4) {
        float v0 = S[i][lane];
        float v1 = (lane < NTOK - 32) ? S[i][lane + 32] : -1e30f;
        float mx = fmaxf(v0, v1);
        #pragma unroll
        for (int o = 16; o; o >>= 1) mx = fmaxf(mx, __shfl_xor_sync(0xffffffffu, mx, o));
        float e0 = __expf(v0 - mx);
        float e1 = (lane < NTOK - 32) ? __expf(v1 - mx) : 0.f;
        float sm = e0 + e1;
        #pragma unroll
        for (int o = 16; o; o >>= 1) sm += __shfl_xor_sync(0xffffffffu, sm, o);
        float inv = 1.f / sm;
        S[i][lane] = e0 * inv;
        if (lane < NTOK - 32) S[i][lane + 32] = e1 * inv;
    }
    __syncthreads();

    // y = S @ v : 49 rows x 4 d-chunks(8), fp32 accumulate
    __half* yout = g_y_h + (size_t)bw * NTOK * CC + h * HD;
    for (int tile = t; tile < NTOK * 4; tile += 128) {
        int i = tile >> 2, d0 = (tile & 3) * 8;
        float acc8[8];
        #pragma unroll
        for (int d = 0; d < 8; d++) acc8[d] = 0.f;
        #pragma unroll 7
        for (int j = 0; j < NTOK; j++) {
            float sv = S[i][j];
            uint4 u = *(const uint4*)(&vs[j][d0]);
            float2 f0 = __half22float2(*(__half2*)&u.x);
            float2 f1 = __half22float2(*(__half2*)&u.y);
            float2 f2 = __half22float2(*(__half2*)&u.z);
            float2 f3 = __half22float2(*(__half2*)&u.w);
            acc8[0] = fmaf(sv, f0.x, acc8[0]); acc8[1] = fmaf(sv, f0.y, acc8[1]);
            acc8[2] = fmaf(sv, f1.x, acc8[2]); acc8[3] = fmaf(sv, f1.y, acc8[3]);
            acc8[4] = fmaf(sv, f2.x, acc8[4]); acc8[5] = fmaf(sv, f2.y, acc8[5]);
            acc8[6] = fmaf(sv, f3.x, acc8[6]); acc8[7] = fmaf(sv, f3.y, acc8[7]);
        }
        __half2* d = (__half2*)(yout + (size_t)i * CC + d0);
        d[0] = __floats2half2_rn(acc8[0], acc8[1]);
        d[1] = __floats2half2_rn(acc8[2], acc8[3]);
        d[2] = __floats2half2_rn(acc8[4], acc8[5]);
        d[3] = __floats2half2_rn(acc8[6], acc8[7]);
    }
}

// ---------------- launch ----------------
extern "C" void kernel_launch(void* const* d_in, const int* in_sizes, int n_in,
                              void* d_out, int out_size)
{
    const float* x1    = (const float*)d_in[0];
    const float* n1g   = (const float*)d_in[2];
    const float* n1b   = (const float*)d_in[3];
    const float* qkvw  = (const float*)d_in[4];
    const float* qkvb  = (const float*)d_in[5];
    const float* projw = (const float*)d_in[6];
    const float* projb = (const float*)d_in[7];
    const float* rpb   = (const float*)d_in[8];
    const float* n2g   = (const float*)d_in[9];
    const float* n2b   = (const float*)d_in[10];
    const float* fc1w  = (const float*)d_in[11];
    const float* fc1b  = (const float*)d_in[12];
    const float* fc2w  = (const float*)d_in[13];
    const float* fc2b  = (const float*)d_in[14];
    float* out = (float*)d_out;
    float* out2 = (out_size >= 2 * BLC) ? out + BLC : nullptr;

    __half *p_xw, *p_qkv, *p_y, *p_xn2, *p_h;
    __half *p_wqkv, *p_wproj, *p_wfc1, *p_wfc2;
    float *p_x1m;
    cudaGetSymbolAddress((void**)&p_xw,   g_xw_h);
    cudaGetSymbolAddress((void**)&p_qkv,  g_qkv_h);
    cudaGetSymbolAddress((void**)&p_y,    g_y_h);
    cudaGetSymbolAddress((void**)&p_x1m,  g_x1m);
    cudaGetSymbolAddress((void**)&p_xn2,  g_xn2_h);
    cudaGetSymbolAddress((void**)&p_h,    g_h_h);
    cudaGetSymbolAddress((void**)&p_wqkv, g_wqkv);
    cudaGetSymbolAddress((void**)&p_wproj,g_wproj);
    cudaGetSymbolAddress((void**)&p_wfc1, g_wfc1);
    cudaGetSymbolAddress((void**)&p_wfc2, g_wfc2);

    cudaFuncSetAttribute(k_gemm_h<0>, cudaFuncAttributeMaxDynamicSharedMemorySize, GEMM_SMEM);
    cudaFuncSetAttribute(k_gemm_h<1>, cudaFuncAttributeMaxDynamicSharedMemorySize, GEMM_SMEM);
    cudaFuncSetAttribute(k_gemm_h<2>, cudaFuncAttributeMaxDynamicSharedMemorySize, GEMM_SMEM);
    cudaFuncSetAttribute(k_gemm_h<3>, cudaFuncAttributeMaxDynamicSharedMemorySize, GEMM_SMEM);

    // 0) weights fp32 -> fp16
    k_f2h_all<<<(NQ_TOT + 255) / 256, 256>>>(qkvw, projw, fc1w, fc2w,
                                             p_wqkv, p_wproj, p_wfc1, p_wfc2);

    // 1) LN1 + shift + window partition
    k_ln1_shift_win<<<MROWS / 8, 256>>>(x1, n1g, n1b);

    // 2) QKV
    k_gemm_h<0><<<dim3(3 * CC / BN, MROWS / BM), 256, GEMM_SMEM>>>(
        p_xw, p_wqkv, qkvb, p_qkv, 3 * CC, CC, nullptr, nullptr);

    // 3) window attention
    k_attn<<<BW * NHD, 128>>>(rpb);

    // 4) proj + window reverse + unshift + residual (+ tuple out y)
    k_gemm_h<3><<<dim3(CC / BN, MROWS / BM), 256, GEMM_SMEM>>>(
        p_y, p_wproj, projb, p_x1m, CC, CC, x1, out2);

    // 5) LN2
    k_ln2<<<MROWS / 8, 256>>>(n2g, n2b);

    // 6) FC1 + GELU
    k_gemm_h<1><<<dim3(HID_ / BN, MROWS / BM), 256, GEMM_SMEM>>>(
        p_xn2, p_wfc1, fc1b, p_h, HID_, CC, nullptr, nullptr);

    // 7) FC2 + residual -> final
    k_gemm_h<2><<<dim3(CC / BN, MROWS / BM), 256, GEMM_SMEM>>>(
        p_h, p_wfc2, fc2b, out, CC, HID_, p_x1m, nullptr);
}

// round 17
// speedup vs baseline: 1.0515x; 1.0515x over previous
#include <cuda_runtime.h>
#include <cuda_fp16.h>
#include <math.h>

// ---------------- problem constants ----------------
#define BB   4
#define TT   4
#define HH   56
#define WW_  56
#define CC   256
#define NHD  8
#define HD   32
#define WS_  7
#define SS_  3
#define NTOK 49
#define HID_ 1024
#define GH   224
#define GW   56
#define NW   256
#define BW   1024
#define MROWS (BW*NTOK)         // 50176
#define LL   (TT*HH*WW_)        // 12544
#define BLC  (BB*LL*CC)         // 12845056

// ---------------- scratch ----------------
__device__ __align__(16) __half g_xw_h [MROWS * CC];
__device__ __align__(16) __half g_qkv_h[MROWS * 3*CC];
__device__ __align__(16) __half g_y_h  [MROWS * CC];
__device__ float g_x1m [BB*LL*CC];
__device__ __align__(16) __half g_xn2_h[BB*LL*CC];
__device__ __align__(16) __half g_h_h  [BB*LL*HID_];
__device__ __align__(16) __half g_wqkv[3*CC*CC];
__device__ __align__(16) __half g_wproj[CC*CC];
__device__ __align__(16) __half g_wfc1[HID_*CC];
__device__ __align__(16) __half g_wfc2[CC*HID_];

// ---------------- fused weight convert ----------------
#define NQ_QKV (3*CC*CC/4)
#define NQ_PROJ (CC*CC/4)
#define NQ_FC1 (HID_*CC/4)
#define NQ_FC2 (CC*HID_/4)
#define NQ_TOT (NQ_QKV+NQ_PROJ+NQ_FC1+NQ_FC2)

__global__ __launch_bounds__(256) void k_f2h_all(
    const float* __restrict__ qkvw, const float* __restrict__ projw,
    const float* __restrict__ fc1w, const float* __restrict__ fc2w,
    __half* __restrict__ dqkv, __half* __restrict__ dproj,
    __half* __restrict__ dfc1, __half* __restrict__ dfc2)
{
    int i = blockIdx.x * 256 + threadIdx.x;
    if (i >= NQ_TOT) return;
    const float* src; __half* dst; int j = i;
    if (j < NQ_QKV)                 { src = qkvw; dst = dqkv; }
    else if ((j -= NQ_QKV) < NQ_PROJ) { src = projw; dst = dproj; }
    else if ((j -= NQ_PROJ) < NQ_FC1) { src = fc1w; dst = dfc1; }
    else { j -= NQ_FC1; src = fc2w; dst = dfc2; }
    float4 v = ((const float4*)src)[j];
    ((__half2*)dst)[2 * j]     = __floats2half2_rn(v.x, v.y);
    ((__half2*)dst)[2 * j + 1] = __floats2half2_rn(v.z, v.w);
}

// ---------------- LN: one warp per row ----------------
__device__ __forceinline__ void warp_ln(const float4 v0, const float4 v1,
                                        float& mean, float& rstd) {
    float s  = v0.x + v0.y + v0.z + v0.w + v1.x + v1.y + v1.z + v1.w;
    float sq = v0.x*v0.x + v0.y*v0.y + v0.z*v0.z + v0.w*v0.w
             + v1.x*v1.x + v1.y*v1.y + v1.z*v1.z + v1.w*v1.w;
    #pragma unroll
    for (int o = 16; o; o >>= 1) {
        s  += __shfl_xor_sync(0xffffffffu, s,  o);
        sq += __shfl_xor_sync(0xffffffffu, sq, o);
    }
    mean = s * (1.0f / CC);
    float var = sq * (1.0f / CC) - mean * mean;
    rstd = rsqrtf(var + 1e-5f);
}
__device__ __forceinline__ void ln_emit_h(__half* dst, float4 v0, float4 v1,
                                          const float4 g0, const float4 g1,
                                          const float4 b0, const float4 b1,
                                          float m, float rs, int lane) {
    float4 o0, o1;
    o0.x = (v0.x - m) * rs * g0.x + b0.x; o0.y = (v0.y - m) * rs * g0.y + b0.y;
    o0.z = (v0.z - m) * rs * g0.z + b0.z; o0.w = (v0.w - m) * rs * g0.w + b0.w;
    o1.x = (v1.x - m) * rs * g1.x + b1.x; o1.y = (v1.y - m) * rs * g1.y + b1.y;
    o1.z = (v1.z - m) * rs * g1.z + b1.z; o1.w = (v1.w - m) * rs * g1.w + b1.w;
    __half2* d0 = (__half2*)(dst + lane * 4);
    d0[0] = __floats2half2_rn(o0.x, o0.y);
    d0[1] = __floats2half2_rn(o0.z, o0.w);
    __half2* d1 = (__half2*)(dst + 128 + lane * 4);
    d1[0] = __floats2half2_rn(o1.x, o1.y);
    d1[1] = __floats2half2_rn(o1.z, o1.w);
}

__global__ __launch_bounds__(256) void k_ln1_shift_win(
    const float* __restrict__ x1, const float* __restrict__ g, const float* __restrict__ b)
{
    int warp = threadIdx.x >> 5, lane = threadIdx.x & 31;
    int row = blockIdx.x * 8 + warp;
    int bw = row / NTOK, n = row - bw * NTOK;
    int bat = bw >> 8, w = bw & 255;
    int hs = (w >> 3) * WS_ + n / WS_;
    int ws = (w & 7) * WS_ + n % WS_;
    int h0 = hs + SS_; if (h0 >= GH) h0 -= GH;
    int w0 = ws + SS_; if (w0 >= GW) w0 -= GW;
    const float4* src = (const float4*)(x1 + ((size_t)bat * LL + (size_t)h0 * GW + w0) * CC);
    float4 v0 = src[lane], v1 = src[lane + 32];
    float m, rs; warp_ln(v0, v1, m, rs);
    float4 g0 = ((const float4*)g)[lane], g1 = ((const float4*)g)[lane + 32];
    float4 b0 = ((const float4*)b)[lane], b1 = ((const float4*)b)[lane + 32];
    ln_emit_h(g_xw_h + (size_t)row * CC, v0, v1, g0, g1, b0, b1, m, rs, lane);
}

__global__ __launch_bounds__(256) void k_ln2(
    const float* __restrict__ g, const float* __restrict__ b)
{
    int warp = threadIdx.x >> 5, lane = threadIdx.x & 31;
    int row = blockIdx.x * 8 + warp;
    const float4* src = (const float4*)(g_x1m + (size_t)row * CC);
    float4 v0 = src[lane], v1 = src[lane + 32];
    float m, rs; warp_ln(v0, v1, m, rs);
    float4 g0 = ((const float4*)g)[lane], g1 = ((const float4*)g)[lane + 32];
    float4 b0 = ((const float4*)b)[lane], b1 = ((const float4*)b)[lane + 32];
    ln_emit_h(g_xn2_h + (size_t)row * CC, v0, v1, g0, g1, b0, b1, m, rs, lane);
}

// ---------------- common helpers ----------------
__device__ __forceinline__ unsigned smem_u32(const void* p) {
    unsigned a;
    asm("{ .reg .u64 t; cvta.to.shared.u64 t, %1; cvt.u32.u64 %0, t; }" : "=r"(a) : "l"(p));
    return a;
}
__device__ __forceinline__ void cp16(unsigned dst, const void* src) {
    asm volatile("cp.async.cg.shared.global [%0], [%1], 16;" :: "r"(dst), "l"(src));
}
#define CP_COMMIT() asm volatile("cp.async.commit_group;" ::: "memory")

__device__ __forceinline__ void mma16816(float* c, const unsigned* a, unsigned b0, unsigned b1) {
    asm volatile("mma.sync.aligned.m16n8k16.row.col.f32.f16.f16.f32 "
                 "{%0,%1,%2,%3}, {%4,%5,%6,%7}, {%8,%9}, {%0,%1,%2,%3};"
                 : "+f"(c[0]), "+f"(c[1]), "+f"(c[2]), "+f"(c[3])
                 : "r"(a[0]), "r"(a[1]), "r"(a[2]), "r"(a[3]), "r"(b0), "r"(b1));
}
__device__ __forceinline__ void ldsm4(unsigned* r, unsigned addr) {
    asm volatile("ldmatrix.sync.aligned.m8n8.x4.shared.b16 {%0,%1,%2,%3}, [%4];"
                 : "=r"(r[0]), "=r"(r[1]), "=r"(r[2]), "=r"(r[3]) : "r"(addr));
}
__device__ __forceinline__ void ldsm4_t(unsigned* r, unsigned addr) {
    asm volatile("ldmatrix.sync.aligned.m8n8.x4.trans.shared.b16 {%0,%1,%2,%3}, [%4];"
                 : "=r"(r[0]), "=r"(r[1]), "=r"(r[2]), "=r"(r[3]) : "r"(addr));
}

// ================= fp16 mma GEMM: BK=32, 4-stage cp.async =================
#define BM 128
#define BN 128
#define BK 32
#define NSTG 4
#define SROW 40
#define MAT_B (BM * SROW * 2)
#define STAGE_B (2 * MAT_B)
#define GEMM_SMEM (NSTG * STAGE_B)

template<int EPI>
__global__ __launch_bounds__(256, 2) void k_gemm_h(
    const __half* __restrict__ A, const __half* __restrict__ Wt,
    const float* __restrict__ bias, void* __restrict__ CoutV,
    int Ntot, int K,
    const float* __restrict__ res, float* __restrict__ out2)
{
    extern __shared__ __half dsm[];
    unsigned sbase = smem_u32(dsm);

    int t = threadIdx.x, lane = t & 31, warp = t >> 5;
    int wm = (warp & 3) * 32, wn = (warp >> 2) * 64;
    int grp = lane >> 2, qid = lane & 3;
    int m0 = blockIdx.y * BM, n0 = blockIdx.x * BN;

    float acc[2][8][4];
    #pragma unroll
    for (int mt = 0; mt < 2; mt++)
        #pragma unroll
        for (int nt = 0; nt < 8; nt++)
            #pragma unroll
            for (int i = 0; i < 4; i++) acc[mt][nt][i] = 0.f;

    int lrow = t >> 2, lseg = t & 3;
    const __half* Ap0 = A  + (size_t)(m0 + lrow) * K + lseg * 8;
    const __half* Ap1 = A  + (size_t)(m0 + lrow + 64) * K + lseg * 8;
    const __half* Bp0 = Wt + (size_t)(n0 + lrow) * K + lseg * 8;
    const __half* Bp1 = Wt + (size_t)(n0 + lrow + 64) * K + lseg * 8;
    unsigned doffA0 = (lrow * SROW + lseg * 8) * 2;
    unsigned doffA1 = ((lrow + 64) * SROW + lseg * 8) * 2;

    int ar = (lane & 7) + ((lane >> 3) & 1) * 8, ac = (lane >> 4) * 8;
    int aoff = (wm + ar) * SROW + ac;
    int br = (lane & 7) + (lane >> 4) * 8, bc = ((lane >> 3) & 1) * 8;
    int boff = (wn + br) * SROW + bc;

    int nk = K / BK;

    #pragma unroll
    for (int s = 0; s < NSTG - 1; s++) {
        unsigned st = sbase + s * STAGE_B;
        int k0 = s * BK;
        cp16(st + doffA0, Ap0 + k0);
        cp16(st + doffA1, Ap1 + k0);
        cp16(st + MAT_B + doffA0, Bp0 + k0);
        cp16(st + MAT_B + doffA1, Bp1 + k0);
        CP_COMMIT();
    }

    for (int ck = 0; ck < nk; ck++) {
        asm volatile("cp.async.wait_group %0;" :: "n"(NSTG - 2) : "memory");
        __syncthreads();
        if (ck + NSTG - 1 < nk) {
            unsigned st = sbase + ((ck + NSTG - 1) & (NSTG - 1)) * STAGE_B;
            int k0 = (ck + NSTG - 1) * BK;
            cp16(st + doffA0, Ap0 + k0);
            cp16(st + doffA1, Ap1 + k0);
            cp16(st + MAT_B + doffA0, Bp0 + k0);
            cp16(st + MAT_B + doffA1, Bp1 + k0);
        }
        CP_COMMIT();

        unsigned aA = sbase + (ck & (NSTG - 1)) * STAGE_B;
        unsigned aB = aA + MAT_B;
        #pragma unroll
        for (int ks = 0; ks < 2; ks++) {
            unsigned a[2][4];
            ldsm4(a[0], aA + (aoff + ks * 16) * 2);
            ldsm4(a[1], aA + (aoff + 16 * SROW + ks * 16) * 2);
            #pragma unroll
            for (int np = 0; np < 4; np++) {
                unsigned bf[4];
                ldsm4(bf, aB + (boff + np * 16 * SROW + ks * 16) * 2);
                mma16816(acc[0][np * 2    ], a[0], bf[0], bf[1]);
                mma16816(acc[0][np * 2 + 1], a[0], bf[2], bf[3]);
                mma16816(acc[1][np * 2    ], a[1], bf[0], bf[1]);
                mma16816(acc[1][np * 2 + 1], a[1], bf[2], bf[3]);
            }
        }
    }

    #pragma unroll
    for (int mt = 0; mt < 2; mt++) {
        #pragma unroll
        for (int half = 0; half < 2; half++) {
            int r = m0 + wm + mt * 16 + grp + half * 8;
            size_t dstrow = 0;
            if (EPI == 3) {
                int bw = r / NTOK, n = r - bw * NTOK;
                int bat = bw >> 8, w = bw & 255;
                int hs = (w >> 3) * WS_ + n / WS_;
                int ws = (w & 7) * WS_ + n % WS_;
                int h0 = hs + SS_; if (h0 >= GH) h0 -= GH;
                int w0 = ws + SS_; if (w0 >= GW) w0 -= GW;
                dstrow = ((size_t)bat * LL + (size_t)h0 * GW + w0) * CC;
            }
            #pragma unroll
            for (int nt = 0; nt < 8; nt++) {
                int c = n0 + wn + nt * 8 + qid * 2;
                float v0 = acc[mt][nt][half * 2 + 0] + bias[c];
                float v1 = acc[mt][nt][half * 2 + 1] + bias[c + 1];
                if (EPI == 0) {
                    *(__half2*)((__half*)CoutV + (size_t)r * Ntot + c) = __floats2half2_rn(v0, v1);
                } else if (EPI == 1) {
                    v0 = 0.5f * v0 * (1.0f + erff(v0 * 0.70710678118654752f));
                    v1 = 0.5f * v1 * (1.0f + erff(v1 * 0.70710678118654752f));
                    *(__half2*)((__half*)CoutV + (size_t)r * Ntot + c) = __floats2half2_rn(v0, v1);
                } else if (EPI == 2) {
                    float* Cout = (float*)CoutV;
                    float2 rr = *(const float2*)(res + (size_t)r * Ntot + c);
                    *(float2*)(Cout + (size_t)r * Ntot + c) = make_float2(rr.x + v0, rr.y + v1);
                } else {
                    float* Cout = (float*)CoutV;
                    size_t off = dstrow + c;
                    if (out2) *(float2*)(out2 + off) = make_float2(v0, v1);
                    float2 rr = *(const float2*)(res + off);
                    *(float2*)(Cout + off) = make_float2(rr.x + v0, rr.y + v1);
                }
            }
        }
    }
}

// ---------------- window attention: scalar QK + softmax, mma PV ----------------
// SP: S (fp32, stride 52) aliased with P (fp16, first 128B of each row, 64 rows)
#define QPH 40    // q/k/v row stride (halves)
#define SPW 52    // SP row stride (floats)

__global__ __launch_bounds__(128, 8) void k_attn(const float* __restrict__ rpb)
{
    int bw = blockIdx.x >> 3;
    int h  = blockIdx.x & 7;
    __shared__ __half qs[52][QPH];
    __shared__ __half ks[52][QPH];
    __shared__ __half vs[64][QPH];
    __shared__ float  SP[64][SPW];
    __shared__ float  bias_s[169];
    __shared__ int    reg_s[52];
    int t = threadIdx.x, lane = t & 31, warp = t >> 5;
    const float scale = 0.17677669529663687f;

    // load q,k,v rows 0..48
    const __half* base = g_qkv_h + (size_t)bw * NTOK * (3 * CC) + h * HD;
    for (int idx = t; idx < 3 * NTOK * 4; idx += 128) {
        int mat = idx / (NTOK * 4), ch = idx - mat * NTOK * 4;
        int n = ch >> 2, seg = ch & 3;
        uint4 u = *(const uint4*)(base + (size_t)n * (3 * CC) + mat * CC + seg * 8);
        __half* dst = (mat == 0 ? &qs[n][0] : mat == 1 ? &ks[n][0] : &vs[n][0]);
        *(uint4*)(dst + seg * 8) = u;
    }
    // zero V pad rows 49..63 (15 rows x 5 chunks of 16B)
    for (int idx = t; idx < 75; idx += 128) {
        int r = 49 + idx / 5, sg = idx % 5;
        *(uint4*)(&vs[r][sg * 8]) = make_uint4(0, 0, 0, 0);
    }
    for (int idx = t; idx < 169; idx += 128) bias_s[idx] = rpb[idx * NHD + h];
    if (t < 52) {
        int rv = 0;
        if (t < NTOK) {
            int w = bw & 255;
            int hs = (w >> 3) * WS_ + t / WS_;
            int ws = (w & 7) * WS_ + t % WS_;
            int rc = hs < (GH - WS_) ? 0 : (hs < (GH - SS_) ? 1 : 2);
            int cc = ws < (GW - WS_) ? 0 : (ws < (GW - SS_) ? 1 : 2);
            rv = rc * 3 + cc;
        }
        reg_s[t] = rv;
    }
    __syncthreads();

    // S = (q @ k^T)*scale + bias + mask : 13x13 tiles of 4x4, fp32 accumulate
    for (int tile = t; tile < 169; tile += 128) {
        int it = tile / 13, jt = tile - it * 13;
        int i0 = it * 4, j0 = jt * 4;
        float a[4][4];
        #pragma unroll
        for (int ii = 0; ii < 4; ii++)
            #pragma unroll
            for (int jj = 0; jj < 4; jj++) a[ii][jj] = 0.f;
        #pragma unroll
        for (int dc = 0; dc < 4; dc++) {
            float qf[4][8], kf[4][8];
            #pragma unroll
            for (int r = 0; r < 4; r++) {
                uint4 u = *(const uint4*)(&qs[i0 + r][dc * 8]);
                float2 f0 = __half22float2(*(__half2*)&u.x);
                float2 f1 = __half22float2(*(__half2*)&u.y);
                float2 f2 = __half22float2(*(__half2*)&u.z);
                float2 f3 = __half22float2(*(__half2*)&u.w);
                qf[r][0]=f0.x; qf[r][1]=f0.y; qf[r][2]=f1.x; qf[r][3]=f1.y;
                qf[r][4]=f2.x; qf[r][5]=f2.y; qf[r][6]=f3.x; qf[r][7]=f3.y;
            }
            #pragma unroll
            for (int r = 0; r < 4; r++) {
                uint4 u = *(const uint4*)(&ks[j0 + r][dc * 8]);
                float2 f0 = __half22float2(*(__half2*)&u.x);
                float2 f1 = __half22float2(*(__half2*)&u.y);
                float2 f2 = __half22float2(*(__half2*)&u.z);
                float2 f3 = __half22float2(*(__half2*)&u.w);
                kf[r][0]=f0.x; kf[r][1]=f0.y; kf[r][2]=f1.x; kf[r][3]=f1.y;
                kf[r][4]=f2.x; kf[r][5]=f2.y; kf[r][6]=f3.x; kf[r][7]=f3.y;
            }
            #pragma unroll
            for (int ii = 0; ii < 4; ii++)
                #pragma unroll
                for (int jj = 0; jj < 4; jj++)
                    #pragma unroll
                    for (int d = 0; d < 8; d++)
                        a[ii][jj] = fmaf(qf[ii][d], kf[jj][d], a[ii][jj]);
        }
        #pragma unroll
        for (int ii = 0; ii < 4; ii++) {
            int i = i0 + ii;
            int yi = i / 7, xi = i - yi * 7, ri = reg_s[i];
            float4 o;
            float* op = &o.x;
            #pragma unroll
            for (int jj = 0; jj < 4; jj++) {
                int j = j0 + jj;
                float s = a[ii][jj] * scale;
                if (i < NTOK && j < NTOK) {
                    int yj = j / 7, xj = j - yj * 7;
                    s += bias_s[(yi - yj + 6) * 13 + (xi - xj + 6)];
                    if (ri != reg_s[j]) s -= 100.f;
                }
                op[jj] = s;
            }
            *(float4*)&SP[i][j0] = o;
        }
    }
    __syncthreads();

    // softmax rows (fp32), write P fp16 in-place (reads complete before writes)
    for (int i = warp; i < NTOK; i += 4) {
        float v0 = SP[i][lane];
        float v1 = (lane < NTOK - 32) ? SP[i][lane + 32] : -1e30f;
        float mx = fmaxf(v0, v1);
        #pragma unroll
        for (int o = 16; o; o >>= 1) mx = fmaxf(mx, __shfl_xor_sync(0xffffffffu, mx, o));
        float e0 = __expf(v0 - mx);
        float e1 = (lane < NTOK - 32) ? __expf(v1 - mx) : 0.f;
        float sm = e0 + e1;
        #pragma unroll
        for (int o = 16; o; o >>= 1) sm += __shfl_xor_sync(0xffffffffu, sm, o);
        float inv = 1.f / sm;
        __half* ph = (__half*)&SP[i][0];
        ph[lane] = __float2half(e0 * inv);
        if (lane < NTOK - 32) ph[lane + 32] = __float2half(e1 * inv);
        if (lane < 15) ph[49 + lane] = __half(0.0f);   // zero pad cols 49..63
    }
    // zero pad cols for rows 49..63 (rows themselves are discarded, but their
    // k-columns 49..63 multiply zero V rows — must be finite)
    for (int i = 49 + warp; i < 64; i += 4) {
        __half* ph = (__half*)&SP[i][0];
        if (lane < 15) ph[49 + lane] = __half(0.0f);
    }
    __syncthreads();

    // PV via mma: warp computes y[wrow:wrow+16][0:32]; P rows stride = 2*SPW halves
    {
        int wrow = warp * 16;
        int grp = lane >> 2, qid = lane & 3;
        int arow = (lane & 7) + ((lane >> 3) & 1) * 8, acol = (lane >> 4) * 8;
        float accO[4][4];
        #pragma unroll
        for (int nt = 0; nt < 4; nt++)
            #pragma unroll
            for (int i = 0; i < 4; i++) accO[nt][i] = 0.f;
        #pragma unroll
        for (int ksx = 0; ksx < 4; ksx++) {
            unsigned a[4];
            ldsm4(a, smem_u32((__half*)&SP[wrow + arow][0] + acol + ksx * 16));
            #pragma unroll
            for (int ng = 0; ng < 2; ng++) {
                unsigned bf[4];
                ldsm4_t(bf, smem_u32(&vs[ksx * 16 + arow][ng * 16 + acol]));
                mma16816(accO[ng * 2    ], a, bf[0], bf[1]);
                mma16816(accO[ng * 2 + 1], a, bf[2], bf[3]);
            }
        }
        __half* yout = g_y_h + (size_t)bw * NTOK * CC + h * HD;
        int i0r = wrow + grp, i1r = wrow + grp + 8;
        #pragma unroll
        for (int nt = 0; nt < 4; nt++) {
            int d = nt * 8 + qid * 2;
            if (i0r < NTOK)
                *(__half2*)(yout + (size_t)i0r * CC + d) = __floats2half2_rn(accO[nt][0], accO[nt][1]);
            if (i1r < NTOK)
                *(__half2*)(yout + (size_t)i1r * CC + d) = __floats2half2_rn(accO[nt][2], accO[nt][3]);
        }
    }
}

// ---------------- launch ----------------
extern "C" void kernel_launch(void* const* d_in, const int* in_sizes, int n_in,
                              void* d_out, int out_size)
{
    const float* x1    = (const float*)d_in[0];
    const float* n1g   = (const float*)d_in[2];
    const float* n1b   = (const float*)d_in[3];
    const float* qkvw  = (const float*)d_in[4];
    const float* qkvb  = (const float*)d_in[5];
    const float* projw = (const float*)d_in[6];
    const float* projb = (const float*)d_in[7];
    const float* rpb   = (const float*)d_in[8];
    const float* n2g   = (const float*)d_in[9];
    const float* n2b   = (const float*)d_in[10];
    const float* fc1w  = (const float*)d_in[11];
    const float* fc1b  = (const float*)d_in[12];
    const float* fc2w  = (const float*)d_in[13];
    const float* fc2b  = (const float*)d_in[14];
    float* out = (float*)d_out;
    float* out2 = (out_size >= 2 * BLC) ? out + BLC : nullptr;

    __half *p_xw, *p_qkv, *p_y, *p_xn2, *p_h;
    __half *p_wqkv, *p_wproj, *p_wfc1, *p_wfc2;
    float *p_x1m;
    cudaGetSymbolAddress((void**)&p_xw,   g_xw_h);
    cudaGetSymbolAddress((void**)&p_qkv,  g_qkv_h);
    cudaGetSymbolAddress((void**)&p_y,    g_y_h);
    cudaGetSymbolAddress((void**)&p_x1m,  g_x1m);
    cudaGetSymbolAddress((void**)&p_xn2,  g_xn2_h);
    cudaGetSymbolAddress((void**)&p_h,    g_h_h);
    cudaGetSymbolAddress((void**)&p_wqkv, g_wqkv);
    cudaGetSymbolAddress((void**)&p_wproj,g_wproj);
    cudaGetSymbolAddress((void**)&p_wfc1, g_wfc1);
    cudaGetSymbolAddress((void**)&p_wfc2, g_wfc2);

    cudaFuncSetAttribute(k_gemm_h<0>, cudaFuncAttributeMaxDynamicSharedMemorySize, GEMM_SMEM);
    cudaFuncSetAttribute(k_gemm_h<1>, cudaFuncAttributeMaxDynamicSharedMemorySize, GEMM_SMEM);
    cudaFuncSetAttribute(k_gemm_h<2>, cudaFuncAttributeMaxDynamicSharedMemorySize, GEMM_SMEM);
    cudaFuncSetAttribute(k_gemm_h<3>, cudaFuncAttributeMaxDynamicSharedMemorySize, GEMM_SMEM);

    // 0) weights fp32 -> fp16
    k_f2h_all<<<(NQ_TOT + 255) / 256, 256>>>(qkvw, projw, fc1w, fc2w,
                                             p_wqkv, p_wproj, p_wfc1, p_wfc2);

    // 1) LN1 + shift + window partition
    k_ln1_shift_win<<<MROWS / 8, 256>>>(x1, n1g, n1b);

    // 2) QKV
    k_gemm_h<0><<<dim3(3 * CC / BN, MROWS / BM), 256, GEMM_SMEM>>>(
        p_xw, p_wqkv, qkvb, p_qkv, 3 * CC, CC, nullptr, nullptr);

    // 3) window attention (hybrid: scalar QK + mma PV)
    k_attn<<<BW * NHD, 128>>>(rpb);

    // 4) proj + window reverse + unshift + residual (+ tuple out y)
    k_gemm_h<3><<<dim3(CC / BN, MROWS / BM), 256, GEMM_SMEM>>>(
        p_y, p_wproj, projb, p_x1m, CC, CC, x1, out2);

    // 5) LN2
    k_ln2<<<MROWS / 8, 256>>>(n2g, n2b);

    // 6) FC1 + GELU
    k_gemm_h<1><<<dim3(HID_ / BN, MROWS / BM), 256, GEMM_SMEM>>>(
        p_xn2, p_wfc1, fc1b, p_h, HID_, CC, nullptr, nullptr);

    // 7) FC2 + residual -> final
    k_gemm_h<2><<<dim3(CC / BN, MROWS / BM), 256, GEMM_SMEM>>>(
        p_h, p_wfc2, fc2b, out, CC, HID_, p_x1m, nullptr);
}